// round 17
// baseline (speedup 1.0000x reference)
#include <cuda_runtime.h>
#include <cuda_fp16.h>
#include <cstdint>

typedef unsigned long long u64;

// Problem constants
#define B_      2048
#define N_      64
#define OBS_    8
#define PRED_   12
#define IN_     6
#define E_      512
#define C_      6
#define CN_     7          // C + 1
#define K_      20
#define DSELF_  120        // IN*(OBS+PRED)
#define DNEI_   48         // IN*OBS
#define RTOT_   (B_ * N_)  // 131072
#define NBLK_   (RTOT_ / 256)   // 512
#define EPSF    1e-4f

#define KP2_    96         // packed A row: [hi(48) | lo(48)] fp16
#define ROW2_   (KP2_ * 2) // 192 bytes per packed A row
#define WROW_   96         // packed W row: [hi(48)] fp16 = 96 bytes
#define X_ELEMS ((size_t)B_ * K_ * E_)   // 20,971,520

// Fixed per-class segments: class c owns rows [c*RTOT_, c*RTOT_+cnt_c).
#define CSEG_ROWS ((size_t)CN_ * RTOT_)   // 917504 rows

// ---------------- scratch (__device__ globals; no allocation) ----------------
__device__ __align__(256) __half g_Ab[CSEG_ROWS * KP2_];            // ~176 MB
__device__ __align__(256) __half g_Wb[(size_t)CN_ * E_ * (WROW_/2)];
__device__ __align__(256) int    g_perm[CSEG_ROWS + 128];
__device__ __align__(256) int    g_cur[CN_];   // zero at launch; reset by GEMM block 0
__device__ __align__(256) float  g_anchor[(size_t)C_ * K_ * E_];
// x-path binning
__device__ __align__(256) int    g_xperm[B_];
__device__ __align__(256) int    g_xcnt[C_];
__device__ __align__(256) int    g_xoff[C_];

// ---------------- kernel 1 (fused): scatter+split | weight split | anchor | xbin ----
#define WPREP_BLKS ((CN_ * E_ + 255) / 256)    // 14
#define ANCH_BLKS  (C_ * K_)                   // 120
#define K1_GRID    (NBLK_ + WPREP_BLKS + ANCH_BLKS + 1)

__global__ void k_fused(const float* __restrict__ neis,
                        const int*   __restrict__ nei_labels,
                        const float* __restrict__ W_nei,
                        const float* __restrict__ init_trajs,
                        const float* __restrict__ W_self,
                        const float* __restrict__ b_self,
                        const int*   __restrict__ self_labels) {
    int tid = threadIdx.x;
    if (blockIdx.x < NBLK_) {
        // ---- scatter + transform + fp16 hi/lo split copy ----
        __shared__ int s_hist[CN_], s_cur[CN_];
        __shared__ int s_pos[256];
        int blk = blockIdx.x;
        if (tid < CN_) s_hist[tid] = 0;
        __syncthreads();
        int row = blk * 256 + tid;
        int c   = nei_labels[row];
        atomicAdd(&s_hist[c], 1);
        __syncthreads();
        if (tid < CN_)
            s_cur[tid] = s_hist[tid] ? atomicAdd(&g_cur[tid], s_hist[tid]) : 0;
        __syncthreads();
        int pos = c * RTOT_ + atomicAdd(&s_cur[c], 1);
        s_pos[tid]  = pos;
        g_perm[pos] = row;
        __syncthreads();

#pragma unroll
        for (int it = 0; it < 12; it++) {
            int idx = it * 256 + tid;
            int r = idx / 12, q = idx % 12;       // q: float4 chunk 0..11
            float4 v = *(const float4*)(neis + ((size_t)blk * 256 + r) * DNEI_ + q * 4);
            v.x = (v.x >= 0.f) ? 1.f / (v.x + EPSF) : 1.f / (v.x - EPSF);
            v.y = (v.y >= 0.f) ? 1.f / (v.y + EPSF) : 1.f / (v.y - EPSF);
            v.z = (v.z >= 0.f) ? 1.f / (v.z + EPSF) : 1.f / (v.z - EPSF);
            v.w = (v.w >= 0.f) ? 1.f / (v.w + EPSF) : 1.f / (v.w - EPSF);

            __half hx = __float2half_rn(v.x), hy = __float2half_rn(v.y);
            __half hz = __float2half_rn(v.z), hw = __float2half_rn(v.w);
            __half lx = __float2half_rn(v.x - __half2float(hx));
            __half ly = __float2half_rn(v.y - __half2float(hy));
            __half lz = __float2half_rn(v.z - __half2float(hz));
            __half lw = __float2half_rn(v.w - __half2float(hw));

            uint32_t h01 = ((uint32_t)__half_as_ushort(hy) << 16) | __half_as_ushort(hx);
            uint32_t h23 = ((uint32_t)__half_as_ushort(hw) << 16) | __half_as_ushort(hz);
            uint32_t l01 = ((uint32_t)__half_as_ushort(ly) << 16) | __half_as_ushort(lx);
            uint32_t l23 = ((uint32_t)__half_as_ushort(lw) << 16) | __half_as_ushort(lz);

            char* rb = (char*)g_Ab + (size_t)s_pos[r] * ROW2_;
            *(uint2*)(rb + q * 8)       = make_uint2(h01, h23);   // hi (k 0..47)
            *(uint2*)(rb + 96 + q * 8)  = make_uint2(l01, l23);   // lo
        }
    } else if (blockIdx.x < NBLK_ + WPREP_BLKS) {
        // ---- weight fp16 hi (only hi needed for the 2-term split) ----
        int g = (blockIdx.x - NBLK_) * 256 + tid;   // (c, n)
        if (g >= CN_ * E_) return;
        int c = g / E_, n = g % E_;
        char* rb = (char*)g_Wb + (size_t)g * WROW_;
        const float* W = W_nei + (size_t)c * DNEI_ * E_ + n;
#pragma unroll 8
        for (int k = 0; k < DNEI_; k++)
            *(__half*)(rb + k * 2) = __float2half_rn(W[(size_t)k * E_]);
    } else if (blockIdx.x < NBLK_ + WPREP_BLKS + ANCH_BLKS) {
        // ---- anchor: anchor[c,k,:] = it[c,k] @ W_self[c][48:] + b_self[c] ----
        int bid = blockIdx.x - NBLK_ - WPREP_BLKS;
        int c  = bid / K_;
        int kk = bid % K_;
        __shared__ float tr[PRED_ * IN_];   // 72
        if (tid < PRED_ * IN_)
            tr[tid] = init_trajs[((size_t)c * K_ + kk) * (PRED_ * IN_) + tid];
        __syncthreads();
        if (tid < 128) {
            int col = tid * 4;
            const float* bb = b_self + (size_t)c * E_ + col;
            float4 acc = *(const float4*)bb;
            const float* W = W_self + ((size_t)c * DSELF_ + DNEI_) * E_ + col;
#pragma unroll 8
            for (int j = 0; j < PRED_ * IN_; j++) {
                float  t = tr[j];
                float4 w = *(const float4*)(W + (size_t)j * E_);
                acc.x += t * w.x; acc.y += t * w.y; acc.z += t * w.z; acc.w += t * w.w;
            }
            *(float4*)(g_anchor + ((size_t)c * K_ + kk) * E_ + col) = acc;
        }
    } else {
        // ---- xbin: bin self_labels (single block, deterministic) ----
        __shared__ int sc2[C_][256];
        __shared__ int s_tot[C_];
        __shared__ int s_off[C_];
        int base = tid * 8;                       // 256 x 8 = 2048
#pragma unroll
        for (int c = 0; c < C_; c++) {
            int n = 0;
#pragma unroll
            for (int i = 0; i < 8; i++) n += (self_labels[base + i] == c);
            sc2[c][tid] = n;
        }
        __syncthreads();
        int w = tid >> 5, lane = tid & 31;
        if (w < C_) {
            int acc = 0;
#pragma unroll
            for (int seg = 0; seg < 8; seg++) {
                int v = sc2[w][seg * 32 + lane];
                int s = v;
#pragma unroll
                for (int d = 1; d < 32; d <<= 1) {
                    int t = __shfl_up_sync(0xffffffffu, s, d);
                    if (lane >= d) s += t;
                }
                sc2[w][seg * 32 + lane] = acc + s - v;
                acc += __shfl_sync(0xffffffffu, s, 31);
            }
            if (lane == 0) s_tot[w] = acc;
        }
        __syncthreads();
        if (tid == 0) {
            int a = 0;
            for (int c = 0; c < C_; c++) {
                s_off[c] = a; g_xoff[c] = a; g_xcnt[c] = s_tot[c]; a += s_tot[c];
            }
        }
        __syncthreads();
#pragma unroll
        for (int c = 0; c < C_; c++) {
            int p = s_off[c] + sc2[c][tid];
#pragma unroll
            for (int i = 0; i < 8; i++)
                if (self_labels[base + i] == c) g_xperm[p++] = base + i;
        }
    }
}

// ================= mma.sync / cp.async helpers =================
__device__ __forceinline__ uint32_t smem_u32(const void* p) {
    uint32_t a;
    asm("{ .reg .u64 t; cvta.to.shared.u64 t, %1; cvt.u32.u64 %0, t; }" : "=r"(a) : "l"(p));
    return a;
}
__device__ __forceinline__ void cp_async16(uint32_t dst, const void* src, int src_size) {
    asm volatile("cp.async.cg.shared.global [%0], [%1], 16, %2;"
                 :: "r"(dst), "l"(src), "r"(src_size) : "memory");
}
__device__ __forceinline__ void cp_commit() {
    asm volatile("cp.async.commit_group;" ::: "memory");
}
__device__ __forceinline__ void cp_wait_all() {
    asm volatile("cp.async.wait_group 0;" ::: "memory");
}
__device__ __forceinline__ void ldsm_x4(uint32_t* r, uint32_t addr) {
    asm volatile("ldmatrix.sync.aligned.m8n8.x4.shared.b16 {%0,%1,%2,%3}, [%4];"
                 : "=r"(r[0]), "=r"(r[1]), "=r"(r[2]), "=r"(r[3]) : "r"(addr));
}
__device__ __forceinline__ void mma16816h(float* c, const uint32_t* a, uint32_t b0, uint32_t b1) {
    asm volatile("mma.sync.aligned.m16n8k16.row.col.f32.f16.f16.f32 "
                 "{%0,%1,%2,%3}, {%4,%5,%6,%7}, {%8,%9}, {%0,%1,%2,%3};"
                 : "+f"(c[0]), "+f"(c[1]), "+f"(c[2]), "+f"(c[3])
                 : "r"(a[0]), "r"(a[1]), "r"(a[2]), "r"(a[3]), "r"(b0), "r"(b1));
}

// Column permutation within each 16-col group (STG.128 epilogue):
//   logical (n8 block j, pos) -> phys x = (pos>>1)*4 + j*2 + (pos&1)
__device__ __forceinline__ int colOf(int row) {
    int g = row & 15, pos = g & 7, j = g >> 3;
    int x = ((pos >> 1) << 2) | (j << 1) | (pos & 1);
    return (row & ~15) | x;
}

// ---------------- kernel 2: persistent GEMM (full-E per CTA) + staggered x ----
#define MT 128
#define NT 128
#define GEMM_MAX_MTILES ((RTOT_ / MT) + CN_)   // 1031
#define JOBS_ 4
#define GEMM_GRID 262                          // >= ceil(1031/4)=258 and >= 262 x-groups
#define STRIDE_A 208                           // conflict-free LDSM stride (A, 192B rows)
#define STRIDE_B 112                           // conflict-free LDSM stride (B, 96B rows)
#define TILE_A   (128 * STRIDE_A)              // 26624
#define TILE_BF  (E_ * STRIDE_B)               // 57344 (full-width B, 512 rows)
// smem: perm 2x512 | bias 2048 | A 2xTILE_A | B TILE_BF | X scratch 1600
#define OFF_PERM  0
#define OFF_BIAS  1024
#define OFF_A     3072
#define OFF_B     (OFF_A + 2 * TILE_A)         // 56320
#define OFF_X     (OFF_B + TILE_BF)            // 113664 (x-phase: rows 32B + obs 1536B)
#define SMEM_BYTES (OFF_X + 1600)              // 115264 (x2 = 230528 <= 233472)
#define XGRP 8

__global__ void __launch_bounds__(256, 2)
k_gemm_mma(const float* __restrict__ b_nei,
           const float* __restrict__ obs,
           const float* __restrict__ W_self,
           float*       __restrict__ out_nei,
           float*       __restrict__ out_x) {
    int mid0 = blockIdx.x * JOBS_;

    int cnts[CN_];
#pragma unroll
    for (int cc = 0; cc < CN_; cc++) cnts[cc] = g_cur[cc];

    extern __shared__ char smem[];
    uint32_t sbase = smem_u32(smem);

    int tid  = threadIdx.x;
    int lane = tid & 31;
    int wid  = tid >> 5;
    int wm   = wid & 1;          // 2 warp rows (64 rows each)
    int wn   = wid >> 1;         // 4 warp cols (32 cols each, within a 128-wide nt)

    // per-thread cp.async geometry
    int pr  = tid >> 1;
    int phA = (tid & 1) * 6;     // A: 12 chunks/row, 6 per thread

    auto map_job = [&](int mid, int& c, int& mt) -> bool {
        int acc = 0;
#pragma unroll
        for (int cc = 0; cc < CN_; cc++) {
            int t = (cnts[cc] + MT - 1) >> 7;
            if (mid < acc + t) { c = cc; mt = mid - acc; return true; }
            acc += t;
        }
        return false;
    };

    auto prefetch_A = [&](int buf, int c, int mt) {
        int m0 = mt * MT;
        int ok = (m0 + pr < cnts[c]) ? 16 : 0;
        const char* src = (const char*)g_Ab
                        + (size_t)(ok ? (c * RTOT_ + m0 + pr) : 0) * ROW2_;
        uint32_t dst = sbase + OFF_A + buf * TILE_A
                     + (uint32_t)pr * STRIDE_A + (uint32_t)phA * 16;
#pragma unroll
        for (int i = 0; i < 6; i++)
            cp_async16(dst + i * 16, src + (phA + i) * 16, ok);
    };
    auto prefetch_perm = [&](int buf, int c, int mt) {
        if (tid < 32) {
            const char* src = (const char*)g_perm + ((size_t)c * RTOT_ + mt * MT) * 4 + tid * 16;
            cp_async16(sbase + OFF_PERM + buf * 512 + tid * 16, src, 16);
        }
    };
    auto prefetch_Bfull = [&](int c) {
#pragma unroll
        for (int rr = 0; rr < 2; rr++) {
            int row = tid * 2 + rr;
            const char* src = (const char*)g_Wb + ((size_t)c * E_ + colOf(row)) * WROW_;
            uint32_t dst = sbase + OFF_B + (uint32_t)row * STRIDE_B;
#pragma unroll
            for (int i = 0; i < 6; i++)
                cp_async16(dst + i * 16, src + i * 16, 16);
        }
        if (tid < 128) {
            const char* src = (const char*)b_nei + (size_t)c * E_ * 4 + tid * 16;
            cp_async16(sbase + OFF_BIAS + tid * 16, src, 16);
        }
    };

    // ---- x-phase (one 8-sample group per CTA), uses dedicated smem at OFF_X ----
    auto do_xphase = [&]() {
        int mid = blockIdx.x;
        int c = -1, gt = 0, acc_t = 0;
#pragma unroll
        for (int cc = 0; cc < C_; cc++) {
            int t = (g_xcnt[cc] + XGRP - 1) / XGRP;
            if (c < 0 && mid < acc_t + t) { c = cc; gt = mid - acc_t; }
            acc_t += t;
        }
        if (c < 0) return;
        int cnt = g_xcnt[c];
        int xo  = g_xoff[c];
        int s0  = gt * XGRP;
        int m   = min(XGRP, cnt - s0);

        int*   s_rows = (int*)(smem + OFF_X);                 // [8] (+pad to 64)
        float (*s_obs)[DNEI_] = (float(*)[DNEI_])(smem + OFF_X + 64);

        __syncthreads();          // protect vs any prior use (none overlap, but cheap)
        if (tid < XGRP)
            s_rows[tid] = (tid < m) ? g_xperm[xo + s0 + tid] : -1;
        __syncthreads();
        if (tid < 96) {
            int s = tid / 12, q = tid % 12;
            int rb = s_rows[s];
            float4 v = make_float4(0.f, 0.f, 0.f, 0.f);
            if (rb >= 0) v = *(const float4*)(obs + (size_t)rb * DNEI_ + q * 4);
            *(float4*)(&s_obs[s][q * 4]) = v;
        }
        __syncthreads();

        int ct   = tid & 127;
        int half = tid >> 7;
        int col  = ct * 4;
        const float* W = W_self + (size_t)c * DSELF_ * E_ + col;
        float4 a0 = make_float4(0,0,0,0), a1 = a0, a2 = a0, a3 = a0;
        float4 a4 = a0, a5 = a0, a6 = a0, a7 = a0;
#pragma unroll 4
        for (int j = 0; j < DNEI_; j++) {
            float4 w4 = *(const float4*)(W + (size_t)j * E_);
            float t0 = s_obs[0][j], t1 = s_obs[1][j], t2 = s_obs[2][j], t3 = s_obs[3][j];
            float t4v = s_obs[4][j], t5 = s_obs[5][j], t6 = s_obs[6][j], t7 = s_obs[7][j];
            a0.x += t0*w4.x; a0.y += t0*w4.y; a0.z += t0*w4.z; a0.w += t0*w4.w;
            a1.x += t1*w4.x; a1.y += t1*w4.y; a1.z += t1*w4.z; a1.w += t1*w4.w;
            a2.x += t2*w4.x; a2.y += t2*w4.y; a2.z += t2*w4.z; a2.w += t2*w4.w;
            a3.x += t3*w4.x; a3.y += t3*w4.y; a3.z += t3*w4.z; a3.w += t3*w4.w;
            a4.x += t4v*w4.x; a4.y += t4v*w4.y; a4.z += t4v*w4.z; a4.w += t4v*w4.w;
            a5.x += t5*w4.x; a5.y += t5*w4.y; a5.z += t5*w4.z; a5.w += t5*w4.w;
            a6.x += t6*w4.x; a6.y += t6*w4.y; a6.z += t6*w4.z; a6.w += t6*w4.w;
            a7.x += t7*w4.x; a7.y += t7*w4.y; a7.z += t7*w4.z; a7.w += t7*w4.w;
        }

        float4 av[XGRP] = {a0, a1, a2, a3, a4, a5, a6, a7};
        int kk0 = half * (K_ / 2), kk1 = kk0 + (K_ / 2);
#pragma unroll
        for (int kk = kk0; kk < kk1; kk++) {
            float4 an = *(const float4*)(g_anchor + ((size_t)c * K_ + kk) * E_ + col);
#pragma unroll
            for (int s = 0; s < XGRP; s++) {
                int rb = s_rows[s];
                if (rb >= 0) {
                    float4 v = make_float4(av[s].x + an.x, av[s].y + an.y,
                                           av[s].z + an.z, av[s].w + an.w);
                    *(float4*)(out_x + ((size_t)rb * K_ + kk) * E_ + col) = v;
                }
            }
        }
    };

    // ---- prologue ----
    int c0, mt0;
    bool have0 = map_job(mid0, c0, mt0);
    if (have0) {
        prefetch_A(0, c0, mt0);
        prefetch_perm(0, c0, mt0);
        prefetch_Bfull(c0);
        cp_commit();
    }

    int cur = 0, bclass = have0 ? c0 : -1;
    int stagger = blockIdx.x & 3;

    for (int j = 0; j < JOBS_; j++) {
        int c, mt;
        bool valid = map_job(mid0 + j, c, mt);     // CTA-uniform

        if (valid) {
            int cnt = cnts[c];

            cp_wait_all();          // this thread's copies for job j done
            __syncthreads();        // all threads' copies + prev compute done

            if (c != bclass) {
                prefetch_Bfull(c);
                cp_commit();
                cp_wait_all();
                __syncthreads();
                bclass = c;
            }

            if (j + 1 < JOBS_) {
                int cn, mtn;
                if (map_job(mid0 + j + 1, cn, mtn)) {
                    prefetch_A(cur ^ 1, cn, mtn);
                    prefetch_perm(cur ^ 1, cn, mtn);
                    cp_commit();
                }
            }

            const int*   s_perm = (const int*)(smem + OFF_PERM + cur * 512);
            const float* s_bias = (const float*)(smem + OFF_BIAS);

            uint32_t a_base = sbase + OFF_A + cur * TILE_A
                            + (uint32_t)(wm * 64 + (lane & 15)) * STRIDE_A
                            + ((lane >> 4) << 4);
            int g = lane >> 2, t4 = lane & 3;
            int m0 = mt * MT;

#pragma unroll
            for (int nt = 0; nt < 4; nt++) {
                uint32_t b_base = sbase + OFF_B
                    + (uint32_t)(nt * NT + wn * 32 + ((lane >> 4) << 3) + (lane & 7)) * STRIDE_B
                    + (((lane >> 3) & 1) << 4);

                float acc[4][4][4];
#pragma unroll
                for (int i = 0; i < 4; i++)
#pragma unroll
                    for (int jj = 0; jj < 4; jj++)
#pragma unroll
                        for (int q = 0; q < 4; q++) acc[i][jj][q] = 0.f;

#pragma unroll
                for (int kc = 0; kc < 3; kc++) {       // 48 = 3 x 16
                    uint32_t kb = kc * 32;
                    uint32_t Bh0[4], Bh1[4];
                    ldsm_x4(Bh0, b_base + kb);
                    ldsm_x4(Bh1, b_base + 16 * STRIDE_B + kb);
#pragma unroll
                    for (int mi = 0; mi < 4; mi++) {
                        uint32_t Ah[4], Al[4];
                        ldsm_x4(Ah, a_base + (uint32_t)mi * 16 * STRIDE_A + kb);
                        ldsm_x4(Al, a_base + (uint32_t)mi * 16 * STRIDE_A + 96 + kb);
                        mma16816h(acc[mi][0], Ah, Bh0[0], Bh0[1]);
                        mma16816h(acc[mi][1], Ah, Bh0[2], Bh0[3]);
                        mma16816h(acc[mi][2], Ah, Bh1[0], Bh1[1]);
                        mma16816h(acc[mi][3], Ah, Bh1[2], Bh1[3]);
                        mma16816h(acc[mi][0], Al, Bh0[0], Bh0[1]);
                        mma16816h(acc[mi][1], Al, Bh0[2], Bh0[3]);
                        mma16816h(acc[mi][2], Al, Bh1[0], Bh1[1]);
                        mma16816h(acc[mi][3], Al, Bh1[2], Bh1[3]);
                    }
                }

                // epilogue: STG.128 on physically-permuted columns
                int cbase = nt * NT + wn * 32;
                float4 b0 = *(const float4*)(s_bias + cbase + t4 * 4);
                float4 b1 = *(const float4*)(s_bias + cbase + 16 + t4 * 4);
#pragma unroll
                for (int mi = 0; mi < 4; mi++) {
#pragma unroll
                    for (int half = 0; half < 2; half++) {
                        int rloc = wm * 64 + mi * 16 + g + half * 8;
                        if (m0 + rloc < cnt) {
                            int rg = s_perm[rloc];
                            float* orow = out_nei + (size_t)rg * E_ + cbase;
                            int h2 = half * 2;
                            float4 v0 = make_float4(
                                acc[mi][0][h2]     + b0.x,
                                acc[mi][0][h2 + 1] + b0.y,
                                acc[mi][1][h2]     + b0.z,
                                acc[mi][1][h2 + 1] + b0.w);
                            float4 v1 = make_float4(
                                acc[mi][2][h2]     + b1.x,
                                acc[mi][2][h2 + 1] + b1.y,
                                acc[mi][3][h2]     + b1.z,
                                acc[mi][3][h2 + 1] + b1.w);
                            *(float4*)(orow + t4 * 4)      = v0;
                            *(float4*)(orow + 16 + t4 * 4) = v1;
                        }
                    }
                }
            }

            cur ^= 1;
        }

        // staggered x-phase: spreads 84 MB of x stores across the GEMM timeline
        if (j == stagger) do_xphase();
    }

    // Reset class counters for the next graph replay (one co-resident wave:
    // every CTA read g_cur in its first microsecond; block 0 resets at the end).
    if (blockIdx.x == 0 && tid < CN_) g_cur[tid] = 0;
}

// ---------------- launcher ----------------
extern "C" void kernel_launch(void* const* d_in, const int* in_sizes, int n_in,
                              void* d_out, int out_size) {
    const float* obs         = (const float*)d_in[0];
    const float* neis        = (const float*)d_in[1];
    const float* init_trajs  = (const float*)d_in[2];
    const float* W_self      = (const float*)d_in[3];
    const float* b_self      = (const float*)d_in[4];
    const float* W_nei       = (const float*)d_in[5];
    const float* b_nei       = (const float*)d_in[6];
    const int*   self_labels = (const int*)d_in[7];
    const int*   nei_labels  = (const int*)d_in[8];

    float* out_x   = (float*)d_out;
    float* out_nei = (float*)d_out + X_ELEMS;

    cudaFuncSetAttribute(k_gemm_mma, cudaFuncAttributeMaxDynamicSharedMemorySize, SMEM_BYTES);

    k_fused<<<K1_GRID, 256>>>(neis, nei_labels, W_nei, init_trajs,
                              W_self, b_self, self_labels);
    k_gemm_mma<<<GEMM_GRID, 256, SMEM_BYTES>>>(b_nei, obs, W_self, out_nei, out_x);
}